// round 12
// baseline (speedup 1.0000x reference)
#include <cuda_runtime.h>
#include <cstdint>
#include <math.h>

#define NB 4
#define NH 16
#define NS 1024
#define ND 64
#define NE 1024

// ---------------------------------------------------------------------------
// Global scratch: bf16 hi/lo packed planes (u32 = 2 bf16, consecutive k).
// ---------------------------------------------------------------------------
__device__ uint32_t g_XH[3 * 4096 * 512];   // inputs  [z][m][kp]
__device__ uint32_t g_XL[3 * 4096 * 512];
__device__ uint32_t g_WH[3 * 1024 * 512];   // weights [z][n][kp]
__device__ uint32_t g_WL[3 * 1024 * 512];
__device__ uint32_t g_QH[NB*NH*NS*32];      // Q/K: [(b,h)][s][dp]
__device__ uint32_t g_QL[NB*NH*NS*32];
__device__ uint32_t g_KH[NB*NH*NS*32];
__device__ uint32_t g_KL[NB*NH*NS*32];
__device__ uint32_t g_VH[NB*NH*64*512];     // V: [(b,h)][d][sp]  (key-pair packed)
__device__ uint32_t g_VL[NB*NH*64*512];

// ---------------------------------------------------------------------------
// helpers
// ---------------------------------------------------------------------------
__device__ __forceinline__ uint32_t smem_u32(const void* p) {
    uint32_t a;
    asm("{ .reg .u64 t; cvta.to.shared.u64 t, %1; cvt.u32.u64 %0, t; }" : "=r"(a) : "l"(p));
    return a;
}
__device__ __forceinline__ void cp16s(uint32_t dst, const void* src) {
    asm volatile("cp.async.cg.shared.global [%0], [%1], 16;" :: "r"(dst), "l"(src));
}
#define CP_COMMIT() asm volatile("cp.async.commit_group;" ::: "memory")
#define CP_WAIT0()  asm volatile("cp.async.wait_group 0;"  ::: "memory")
#define CP_WAIT1()  asm volatile("cp.async.wait_group 1;"  ::: "memory")

__device__ __forceinline__ uint32_t packbf(float e0, float e1) {
    uint32_t r; asm("cvt.rn.bf16x2.f32 %0, %1, %2;" : "=r"(r) : "f"(e1), "f"(e0)); return r;
}
__device__ __forceinline__ void split2(float x0, float x1, uint32_t& h, uint32_t& l) {
    h = packbf(x0, x1);
    float h0 = __uint_as_float(h << 16);
    float h1 = __uint_as_float(h & 0xffff0000u);
    l = packbf(x0 - h0, x1 - h1);
}

// bf16 m16n8k16 mma.sync
__device__ __forceinline__ void mma16(float* d, const uint32_t* a, const uint32_t* b) {
    asm volatile(
        "mma.sync.aligned.m16n8k16.row.col.f32.bf16.bf16.f32 "
        "{%0,%1,%2,%3}, {%4,%5,%6,%7}, {%8,%9}, {%0,%1,%2,%3};"
        : "+f"(d[0]), "+f"(d[1]), "+f"(d[2]), "+f"(d[3])
        : "r"(a[0]), "r"(a[1]), "r"(a[2]), "r"(a[3]), "r"(b[0]), "r"(b[1]));
}

// ldmatrix x4
__device__ __forceinline__ void ldsm4(uint32_t* r, uint32_t addr) {
    asm volatile("ldmatrix.sync.aligned.m8n8.x4.shared.b16 {%0,%1,%2,%3}, [%4];"
        : "=r"(r[0]), "=r"(r[1]), "=r"(r[2]), "=r"(r[3]) : "r"(addr));
}

// ---------------------------------------------------------------------------
// Pre-pass: split 6 fp32 tensors into bf16 hi/lo packed planes.
// ---------------------------------------------------------------------------
__global__ void split_in(const float* __restrict__ q, const float* __restrict__ k,
                         const float* __restrict__ v, const float* __restrict__ wq,
                         const float* __restrict__ wk, const float* __restrict__ wv)
{
    const int z = blockIdx.y;
    const float* src; uint32_t* H; uint32_t* L; int n;
    if (z < 3) {
        src = (z == 0) ? q : (z == 1) ? k : v;
        H = g_XH + (size_t)z * 4096 * 512; L = g_XL + (size_t)z * 4096 * 512;
        n = 4096 * 512;
    } else {
        src = (z == 3) ? wq : (z == 4) ? wk : wv;
        H = g_WH + (size_t)(z - 3) * 1024 * 512; L = g_WL + (size_t)(z - 3) * 1024 * 512;
        n = 1024 * 512;
    }
    for (int i = blockIdx.x * blockDim.x + threadIdx.x; i < n; i += gridDim.x * blockDim.x) {
        float2 x = ((const float2*)src)[i];
        uint32_t h, l; split2(x.x, x.y, h, l);
        H[i] = h; L[i] = l;
    }
}

// ---------------------------------------------------------------------------
// bf16x3 projection, v3: ONE barrier per K-iteration (R11-proven reorder:
// wait own group -> barrier publishes stage it AND proves stage (it+1)%2
// free -> prefetch -> compute). 2 stages, 2 CTAs/SM, ldmatrix frags.
// ---------------------------------------------------------------------------
#define PSTR 20
#define PLSZ (128*PSTR)
#define PSTG (4*PLSZ)
#define PNIT 32

__device__ __forceinline__ void pstage(uint32_t sbase, const uint32_t* __restrict__ XH,
                                       const uint32_t* __restrict__ XL,
                                       const uint32_t* __restrict__ WH,
                                       const uint32_t* __restrict__ WL,
                                       int m0, int n0, int it, int tid)
{
    #pragma unroll
    for (int i = 0; i < 2; i++) {
        int e = tid + i * 256;
        int r = e >> 2, c = e & 3;
        uint32_t o = (uint32_t)(r * PSTR + c * 4) * 4;
        const size_t gi = (size_t)(m0 + r) * 512 + it * 16 + c * 4;
        cp16s(sbase + o,              XH + gi);
        cp16s(sbase + PLSZ*4 + o,     XL + gi);
        const size_t gw = (size_t)(n0 + r) * 512 + it * 16 + c * 4;
        cp16s(sbase + 2*PLSZ*4 + o,   WH + gw);
        cp16s(sbase + 3*PLSZ*4 + o,   WL + gw);
    }
}

__global__ __launch_bounds__(256, 2) void proj_tc(
    const float* __restrict__ Bq, const float* __restrict__ Bk, const float* __restrict__ Bv)
{
    extern __shared__ uint32_t sm[];
    const uint32_t sb = smem_u32(sm);

    const int tid = threadIdx.x;
    const int z = blockIdx.z;
    const uint32_t* XH = g_XH + (size_t)z * 4096 * 512;
    const uint32_t* XL = g_XL + (size_t)z * 4096 * 512;
    const uint32_t* WH = g_WH + (size_t)z * 1024 * 512;
    const uint32_t* WL = g_WL + (size_t)z * 1024 * 512;
    const float* Bi = (z == 0) ? Bq : (z == 1) ? Bk : Bv;
    const float scale = (z == 0) ? 0.125f : 1.0f;

    const int m0 = blockIdx.y * 128;
    const int n0 = blockIdx.x * 128;

    const int warp = tid >> 5, lane = tid & 31;
    const int g = lane >> 2, tig = lane & 3;
    const int wm = warp >> 1, wn = warp & 1;
    const int mid = lane >> 3, lr = lane & 7;
    const int arowl = (mid & 1) * 8 + lr, acol = (mid >> 1) * 4;
    const int browl = (mid >> 1) * 8 + lr, bcol = (mid & 1) * 4;

    float cfr[2][8][4];
    #pragma unroll
    for (int mt = 0; mt < 2; mt++)
        #pragma unroll
        for (int nt = 0; nt < 8; nt++)
            #pragma unroll
            for (int e = 0; e < 4; e++) cfr[mt][nt][e] = 0.f;

    pstage(sb, XH, XL, WH, WL, m0, n0, 0, tid);
    CP_COMMIT();

    for (int it = 0; it < PNIT; it++) {
        CP_WAIT0();            // stage it%2 landed (own copies)
        __syncthreads();       // publish stage it; stage (it+1)%2 provably free
        if (it + 1 < PNIT)
            pstage(sb + ((it + 1) & 1) * PSTG * 4, XH, XL, WH, WL, m0, n0, it + 1, tid);
        CP_COMMIT();

        const uint32_t AHb = sb + ((it & 1) * PSTG) * 4;
        const uint32_t ALb = AHb + PLSZ * 4;
        const uint32_t BHb = AHb + 2 * PLSZ * 4;
        const uint32_t BLb = AHb + 3 * PLSZ * 4;

        #pragma unroll
        for (int kg = 0; kg < 2; kg++) {
            const int kgb = kg * 8;
            uint32_t ah[2][4], al[2][4];
            #pragma unroll
            for (int mt = 0; mt < 2; mt++) {
                const uint32_t oa = (uint32_t)((wm*32 + mt*16 + arowl) * PSTR + kgb + acol) * 4;
                ldsm4(ah[mt], AHb + oa);
                ldsm4(al[mt], ALb + oa);
            }
            #pragma unroll
            for (int np = 0; np < 4; np++) {
                const int nt0 = 2 * np;
                const uint32_t ob = (uint32_t)((wn*64 + nt0*8 + browl) * PSTR + kgb + bcol) * 4;
                uint32_t bh[4], bl[4];
                ldsm4(bh, BHb + ob);
                ldsm4(bl, BLb + ob);
                #pragma unroll
                for (int mt = 0; mt < 2; mt++) {
                    mma16(cfr[mt][nt0],   ah[mt], bl);
                    mma16(cfr[mt][nt0],   al[mt], bh);
                    mma16(cfr[mt][nt0],   ah[mt], bh);
                    mma16(cfr[mt][nt0+1], ah[mt], bl + 2);
                    mma16(cfr[mt][nt0+1], al[mt], bh + 2);
                    mma16(cfr[mt][nt0+1], ah[mt], bh + 2);
                }
            }
        }
        // no trailing barrier: next iteration's leading barrier covers reuse
    }
    __syncthreads();           // all compute done before Cs overwrites stages

    float* Cs = (float*)sm;
    #pragma unroll
    for (int mt = 0; mt < 2; mt++) {
        const int rm = wm * 32 + mt * 16 + g;
        #pragma unroll
        for (int nt = 0; nt < 8; nt++) {
            const int cn = wn * 64 + nt * 8 + 2 * tig;
            Cs[(rm    ) * 132 + cn    ] = cfr[mt][nt][0];
            Cs[(rm    ) * 132 + cn + 1] = cfr[mt][nt][1];
            Cs[(rm + 8) * 132 + cn    ] = cfr[mt][nt][2];
            Cs[(rm + 8) * 132 + cn + 1] = cfr[mt][nt][3];
        }
    }
    __syncthreads();

    if (z < 2) {
        uint32_t* OH = (z == 0) ? g_QH : g_KH;
        uint32_t* OL = (z == 0) ? g_QL : g_KL;
        const int qcol = (tid & 15) * 4;
        #pragma unroll
        for (int hh = 0; hh < 2; hh++) {
            const int h = ((n0 + hh * 64) >> 6);
            const float4 bv = *(const float4*)(Bi + n0 + hh * 64 + qcol);
            #pragma unroll
            for (int p = 0; p < 8; p++) {
                const int idx = tid + p * 256;
                const int m = idx >> 4;
                const int gm = m0 + m, b = gm >> 10, s = gm & (NS - 1);
                const float* src = Cs + m * 132 + hh * 64 + qcol;
                float v0 = (src[0] + bv.x) * scale;
                float v1 = (src[1] + bv.y) * scale;
                float v2 = (src[2] + bv.z) * scale;
                float v3 = (src[3] + bv.w) * scale;
                uint32_t h0, l0, h1, l1;
                split2(v0, v1, h0, l0);
                split2(v2, v3, h1, l1);
                const size_t o = ((size_t)(b * NH + h) * NS + s) * 32 + (qcol >> 1);
                *(uint2*)(OH + o) = make_uint2(h0, h1);
                *(uint2*)(OL + o) = make_uint2(l0, l1);
            }
        }
    } else {
        #pragma unroll 1
        for (int p = 0; p < 32; p++) {
            const int e = tid + p * 256;
            const int sp = e & 63;
            const int dl = e >> 6;
            const int n = n0 + dl;
            const int h = n >> 6, dd = n & 63;
            const int gm = m0 + 2 * sp;
            const int b = gm >> 10;
            const int spg = (gm & (NS - 1)) >> 1;
            const float bi = Bi[n];
            float v0 = Cs[(2*sp    ) * 132 + dl] + bi;
            float v1 = Cs[(2*sp + 1) * 132 + dl] + bi;
            uint32_t hh, ll;
            split2(v0, v1, hh, ll);
            const size_t o = ((size_t)(b * NH + h) * 64 + dd) * 512 + spg;
            g_VH[o] = hh;
            g_VL[o] = ll;
        }
    }
}

// ---------------------------------------------------------------------------
// bf16x3 flash attention, v5: R11 structure + next-tile mask L2 prefetch.
// ---------------------------------------------------------------------------
#define ASTR 36
#define APL (64*ASTR)
#define ASTG (4*APL)
#define NSTAGE 3

__device__ __forceinline__ void aload(uint32_t sb, int stage, int j0,
                                      const uint32_t* __restrict__ KHg,
                                      const uint32_t* __restrict__ KLg,
                                      const uint32_t* __restrict__ VHg,
                                      const uint32_t* __restrict__ VLg, int tid)
{
    const uint32_t base = sb + (uint32_t)stage * ASTG * 4;
    #pragma unroll
    for (int i = 0; i < 2; i++) {
        int e = tid + i * 256;
        int r = e >> 3, c = e & 7;
        uint32_t o = (uint32_t)(r * ASTR + c * 4) * 4;
        const size_t gk = (size_t)(j0 + r) * 32 + c * 4;
        cp16s(base + o,            KHg + gk);
        cp16s(base + APL*4 + o,    KLg + gk);
        const size_t gv = (size_t)r * 512 + (j0 >> 1) + c * 4;
        cp16s(base + 2*APL*4 + o,  VHg + gv);
        cp16s(base + 3*APL*4 + o,  VLg + gv);
    }
}

__global__ __launch_bounds__(256, 2) void attn_tc(const float* __restrict__ mask,
                                                  float* __restrict__ out)
{
    extern __shared__ uint32_t s[];
    const uint32_t sb = smem_u32(s);

    const int b = blockIdx.z, h = blockIdx.y;
    const int q0 = blockIdx.x * 128;
    const int tid = threadIdx.x, warp = tid >> 5, lane = tid & 31;
    const int g = lane >> 2, tig = lane & 3;
    const int r0 = warp * 16 + g;
    const int mid = lane >> 3, lr = lane & 7;
    const int browl = (mid >> 1) * 8 + lr, bcol = (mid & 1) * 4;

    const size_t bh32 = (size_t)(b * NH + h) * NS * 32;
    const uint32_t* QHg = g_QH + bh32;
    const uint32_t* QLg = g_QL + bh32;
    const uint32_t* KHg = g_KH + bh32;
    const uint32_t* KLg = g_KL + bh32;
    const size_t bhv = (size_t)(b * NH + h) * 64 * 512;
    const uint32_t* VHg = g_VH + bhv;
    const uint32_t* VLg = g_VL + bhv;
    // per-thread mask prefetch address pattern: row tid>>1, half-line tid&1
    const float* mpref = mask + ((size_t)b*NS + q0 + (tid >> 1))*NS + (tid & 1)*32;

    // --- Q bounce through stage0/1 KH/KL planes, then frags -> registers ---
    #pragma unroll
    for (int i = 0; i < 4; i++) {
        int e = tid + i * 256;
        int vr = e >> 3, c = e & 7;
        uint32_t idx = (uint32_t)(vr >> 6) * ASTG + (uint32_t)(vr & 63) * ASTR + c * 4;
        *(uint4*)(s + idx)       = *(const uint4*)(QHg + (size_t)(q0 + vr) * 32 + c * 4);
        *(uint4*)(s + idx + APL) = *(const uint4*)(QLg + (size_t)(q0 + vr) * 32 + c * 4);
    }
    __syncthreads();
    uint32_t qh[4][4], ql[4][4];
    {
        const uint32_t qbase = (uint32_t)(r0 >> 6) * ASTG;
        const int lrq = r0 & 63;
        #pragma unroll
        for (int kg = 0; kg < 4; kg++) {
            const int kp1 = kg * 8 + tig, kp2 = kp1 + 4;
            qh[kg][0] = s[qbase + lrq*ASTR + kp1]; qh[kg][1] = s[qbase + (lrq+8)*ASTR + kp1];
            qh[kg][2] = s[qbase + lrq*ASTR + kp2]; qh[kg][3] = s[qbase + (lrq+8)*ASTR + kp2];
            ql[kg][0] = s[qbase + APL + lrq*ASTR + kp1]; ql[kg][1] = s[qbase + APL + (lrq+8)*ASTR + kp1];
            ql[kg][2] = s[qbase + APL + lrq*ASTR + kp2]; ql[kg][3] = s[qbase + APL + (lrq+8)*ASTR + kp2];
        }
    }
    __syncthreads();

    float o[8][4];
    #pragma unroll
    for (int nt = 0; nt < 8; nt++)
        #pragma unroll
        for (int e = 0; e < 4; e++) o[nt][e] = 0.f;
    float mrow[2] = {-3.4e38f, -3.4e38f};
    float lsum[2] = {0.f, 0.f};

    aload(sb, 0, 0, KHg, KLg, VHg, VLg, tid);
    CP_COMMIT();
    aload(sb, 1, 64, KHg, KLg, VHg, VLg, tid);
    CP_COMMIT();
    asm volatile("prefetch.global.L2 [%0];" :: "l"(mpref));   // tile 0 mask

    for (int jt = 0; jt < NS/64; jt++) {
        CP_WAIT1();            // own copies of stage jt%3 have landed
        __syncthreads();       // publishes stage jt; proves stage (jt+2)%3 free
        if (jt + 2 < NS/64)
            aload(sb, (jt + 2) % NSTAGE, (jt + 2) * 64, KHg, KLg, VHg, VLg, tid);
        CP_COMMIT();           // unconditional: uniform group counts
        if (jt + 1 < NS/64)    // warm L2 for next tile's mask slab (32 KB)
            asm volatile("prefetch.global.L2 [%0];" :: "l"(mpref + (jt + 1) * 64));

        const uint32_t KHb = sb + ((jt % NSTAGE) * ASTG) * 4;
        const uint32_t KLb = KHb + APL * 4;
        const uint32_t VHb = KHb + 2 * APL * 4;
        const uint32_t VLb = KHb + 3 * APL * 4;
        const int j0 = jt * 64;

        // ---- scores S[16x64] per warp, bf16x3, ldmatrix B-frags ----
        float c[8][4];
        #pragma unroll
        for (int nt = 0; nt < 8; nt++)
            #pragma unroll
            for (int e = 0; e < 4; e++) c[nt][e] = 0.f;

        #pragma unroll
        for (int kg = 0; kg < 4; kg++) {
            const int kgb = kg * 8;
            #pragma unroll
            for (int np = 0; np < 4; np++) {
                const int nt0 = 2 * np;
                const uint32_t ob = (uint32_t)((nt0*8 + browl) * ASTR + kgb + bcol) * 4;
                uint32_t kh[4], kl[4];
                ldsm4(kh, KHb + ob);
                ldsm4(kl, KLb + ob);
                mma16(c[nt0],   qh[kg], kl);
                mma16(c[nt0],   ql[kg], kh);
                mma16(c[nt0],   qh[kg], kh);
                mma16(c[nt0+1], qh[kg], kl + 2);
                mma16(c[nt0+1], ql[kg], kh + 2);
                mma16(c[nt0+1], qh[kg], kh + 2);
            }
        }

        // ---- mask ----
        const float* mr = mask + ((size_t)b*NS + (q0 + r0))*NS + j0 + 2*tig;
        #pragma unroll
        for (int nt = 0; nt < 8; nt++) {
            float2 m0v = *(const float2*)(mr + nt*8);
            float2 m1v = *(const float2*)(mr + (size_t)8*NS + nt*8);
            c[nt][0] = fmaf(m0v.x - 1.f, 1e6f, c[nt][0]);
            c[nt][1] = fmaf(m0v.y - 1.f, 1e6f, c[nt][1]);
            c[nt][2] = fmaf(m1v.x - 1.f, 1e6f, c[nt][2]);
            c[nt][3] = fmaf(m1v.y - 1.f, 1e6f, c[nt][3]);
        }

        // ---- online softmax ----
        #pragma unroll
        for (int sl = 0; sl < 2; sl++) {
            float cm = -3.4e38f;
            #pragma unroll
            for (int nt = 0; nt < 8; nt++)
                cm = fmaxf(cm, fmaxf(c[nt][2*sl], c[nt][2*sl + 1]));
            cm = fmaxf(cm, __shfl_xor_sync(0xffffffffu, cm, 1));
            cm = fmaxf(cm, __shfl_xor_sync(0xffffffffu, cm, 2));
            const float mn = fmaxf(mrow[sl], cm);
            const float alc = __expf(mrow[sl] - mn);
            mrow[sl] = mn;
            float rs = 0.f;
            #pragma unroll
            for (int nt = 0; nt < 8; nt++) {
                c[nt][2*sl]     = __expf(c[nt][2*sl]     - mn);
                c[nt][2*sl + 1] = __expf(c[nt][2*sl + 1] - mn);
                rs += c[nt][2*sl] + c[nt][2*sl + 1];
            }
            rs += __shfl_xor_sync(0xffffffffu, rs, 1);
            rs += __shfl_xor_sync(0xffffffffu, rs, 2);
            lsum[sl] = lsum[sl] * alc + rs;
            #pragma unroll
            for (int nt = 0; nt < 8; nt++) {
                o[nt][2*sl]     *= alc;
                o[nt][2*sl + 1] *= alc;
            }
        }

        // ---- O += P @ V, ldmatrix V-frags ----
        #pragma unroll
        for (int q = 0; q < 4; q++) {
            uint32_t ph[4], pl[4];
            split2(c[2*q    ][0], c[2*q    ][1], ph[0], pl[0]);
            split2(c[2*q    ][2], c[2*q    ][3], ph[1], pl[1]);
            split2(c[2*q + 1][0], c[2*q + 1][1], ph[2], pl[2]);
            split2(c[2*q + 1][2], c[2*q + 1][3], ph[3], pl[3]);
            const int jb = q * 8;
            #pragma unroll
            for (int np = 0; np < 4; np++) {
                const int nt0 = 2 * np;
                const uint32_t ob = (uint32_t)((nt0*8 + browl) * ASTR + jb + bcol) * 4;
                uint32_t vh[4], vl[4];
                ldsm4(vh, VHb + ob);
                ldsm4(vl, VLb + ob);
                mma16(o[nt0],   ph, vl);
                mma16(o[nt0],   pl, vh);
                mma16(o[nt0],   ph, vh);
                mma16(o[nt0+1], ph, vl + 2);
                mma16(o[nt0+1], pl, vh + 2);
                mma16(o[nt0+1], ph, vh + 2);
            }
        }
        // no trailing barrier: next iteration's leading barrier + 3-stage ring
    }

    // ---- epilogue ----
    const float inv0 = 1.0f / lsum[0];
    const float inv1 = 1.0f / lsum[1];
    float* orow = out + ((size_t)b*NS + (q0 + r0))*NE + h*ND + 2*tig;
    #pragma unroll
    for (int nt = 0; nt < 8; nt++) {
        *(float2*)(orow + nt*8) = make_float2(o[nt][0]*inv0, o[nt][1]*inv0);
        *(float2*)(orow + (size_t)8*NE + nt*8) = make_float2(o[nt][2]*inv1, o[nt][3]*inv1);
    }
}

extern "C" void kernel_launch(void* const* d_in, const int* in_sizes, int n_in,
                              void* d_out, int out_size)
{
    const float* query = (const float*)d_in[0];
    const float* key   = (const float*)d_in[1];
    const float* value = (const float*)d_in[2];
    const float* mask  = (const float*)d_in[3];
    const float* Wq    = (const float*)d_in[4];
    const float* bq    = (const float*)d_in[5];
    const float* Wk    = (const float*)d_in[6];
    const float* bk    = (const float*)d_in[7];
    const float* Wv    = (const float*)d_in[8];
    const float* bv    = (const float*)d_in[9];
    float* out = (float*)d_out;

    split_in<<<dim3(512, 6), 256>>>(query, key, value, Wq, Wk, Wv);

    const int proj_smem = 2 * PSTG * 4;   // 81920 B
    cudaFuncSetAttribute(proj_tc, cudaFuncAttributeMaxDynamicSharedMemorySize, proj_smem);
    dim3 pg(NE / 128, (NB * NS) / 128, 3);
    proj_tc<<<pg, 256, proj_smem>>>(bq, bk, bv);

    const int attn_smem = NSTAGE * ASTG * 4;   // 110592 B
    cudaFuncSetAttribute(attn_tc, cudaFuncAttributeMaxDynamicSharedMemorySize, attn_smem);
    dim3 ag(NS/128, NH, NB);
    attn_tc<<<ag, 256, attn_smem>>>(mask, out);
}

// round 13
// speedup vs baseline: 1.0762x; 1.0762x over previous
#include <cuda_runtime.h>
#include <cstdint>
#include <math.h>

#define NB 4
#define NH 16
#define NS 1024
#define ND 64
#define NE 1024

// ---------------------------------------------------------------------------
// Global scratch: bf16 hi/lo packed planes (u32 = 2 bf16, consecutive k).
// ---------------------------------------------------------------------------
__device__ uint32_t g_XH[3 * 4096 * 512];   // inputs  [z][m][kp]
__device__ uint32_t g_XL[3 * 4096 * 512];
__device__ uint32_t g_WH[3 * 1024 * 512];   // weights [z][n][kp]
__device__ uint32_t g_WL[3 * 1024 * 512];
__device__ uint32_t g_QH[NB*NH*NS*32];      // Q/K: [(b,h)][s][dp]
__device__ uint32_t g_QL[NB*NH*NS*32];
__device__ uint32_t g_KH[NB*NH*NS*32];
__device__ uint32_t g_KL[NB*NH*NS*32];
__device__ uint32_t g_VH[NB*NH*64*512];     // V: [(b,h)][d][sp]  (key-pair packed)
__device__ uint32_t g_VL[NB*NH*64*512];
__device__ uint32_t g_MB[NB*NS*32];         // mask bits: [b][q_row][key_word]

// ---------------------------------------------------------------------------
// helpers
// ---------------------------------------------------------------------------
__device__ __forceinline__ uint32_t smem_u32(const void* p) {
    uint32_t a;
    asm("{ .reg .u64 t; cvta.to.shared.u64 t, %1; cvt.u32.u64 %0, t; }" : "=r"(a) : "l"(p));
    return a;
}
__device__ __forceinline__ void cp16s(uint32_t dst, const void* src) {
    asm volatile("cp.async.cg.shared.global [%0], [%1], 16;" :: "r"(dst), "l"(src));
}
#define CP_COMMIT() asm volatile("cp.async.commit_group;" ::: "memory")
#define CP_WAIT1()  asm volatile("cp.async.wait_group 1;"  ::: "memory")

__device__ __forceinline__ uint32_t packbf(float e0, float e1) {
    uint32_t r; asm("cvt.rn.bf16x2.f32 %0, %1, %2;" : "=r"(r) : "f"(e1), "f"(e0)); return r;
}
__device__ __forceinline__ void split2(float x0, float x1, uint32_t& h, uint32_t& l) {
    h = packbf(x0, x1);
    float h0 = __uint_as_float(h << 16);
    float h1 = __uint_as_float(h & 0xffff0000u);
    l = packbf(x0 - h0, x1 - h1);
}

// bf16 m16n8k16 mma.sync
__device__ __forceinline__ void mma16(float* d, const uint32_t* a, const uint32_t* b) {
    asm volatile(
        "mma.sync.aligned.m16n8k16.row.col.f32.bf16.bf16.f32 "
        "{%0,%1,%2,%3}, {%4,%5,%6,%7}, {%8,%9}, {%0,%1,%2,%3};"
        : "+f"(d[0]), "+f"(d[1]), "+f"(d[2]), "+f"(d[3])
        : "r"(a[0]), "r"(a[1]), "r"(a[2]), "r"(a[3]), "r"(b[0]), "r"(b[1]));
}

// ldmatrix x4
__device__ __forceinline__ void ldsm4(uint32_t* r, uint32_t addr) {
    asm volatile("ldmatrix.sync.aligned.m8n8.x4.shared.b16 {%0,%1,%2,%3}, [%4];"
        : "=r"(r[0]), "=r"(r[1]), "=r"(r[2]), "=r"(r[3]) : "r"(addr));
}

// ---------------------------------------------------------------------------
// Pre-pass: split 6 fp32 tensors into bf16 hi/lo planes; bitpack the mask.
// blockIdx.y: 0..2 inputs, 3..5 weights, 6 mask.
// ---------------------------------------------------------------------------
__global__ void split_in(const float* __restrict__ q, const float* __restrict__ k,
                         const float* __restrict__ v, const float* __restrict__ wq,
                         const float* __restrict__ wk, const float* __restrict__ wv,
                         const float* __restrict__ mk)
{
    const int z = blockIdx.y;
    if (z == 6) {
        // mask -> 1 bit per entry: word i covers flat entries [32i, 32i+32)
        const int nwords = NB * NS * 32;
        for (int i = blockIdx.x * blockDim.x + threadIdx.x; i < nwords;
             i += gridDim.x * blockDim.x) {
            const float4* msrc = (const float4*)(mk + (size_t)i * 32);
            uint32_t w = 0;
            #pragma unroll
            for (int qd = 0; qd < 8; qd++) {
                float4 m4 = msrc[qd];
                w |= (m4.x > 0.5f ? 1u : 0u) << (4*qd);
                w |= (m4.y > 0.5f ? 2u : 0u) << (4*qd);
                w |= (m4.z > 0.5f ? 4u : 0u) << (4*qd);
                w |= (m4.w > 0.5f ? 8u : 0u) << (4*qd);
            }
            g_MB[i] = w;
        }
        return;
    }
    const float* src; uint32_t* H; uint32_t* L; int n;
    if (z < 3) {
        src = (z == 0) ? q : (z == 1) ? k : v;
        H = g_XH + (size_t)z * 4096 * 512; L = g_XL + (size_t)z * 4096 * 512;
        n = 4096 * 512;
    } else {
        src = (z == 3) ? wq : (z == 4) ? wk : wv;
        H = g_WH + (size_t)(z - 3) * 1024 * 512; L = g_WL + (size_t)(z - 3) * 1024 * 512;
        n = 1024 * 512;
    }
    for (int i = blockIdx.x * blockDim.x + threadIdx.x; i < n; i += gridDim.x * blockDim.x) {
        float2 x = ((const float2*)src)[i];
        uint32_t h, l; split2(x.x, x.y, h, l);
        H[i] = h; L[i] = l;
    }
}

// ---------------------------------------------------------------------------
// bf16x3 projection (R11-proven version: prefetch-first, WAIT1, 2 barriers).
// ---------------------------------------------------------------------------
#define PSTR 20
#define PLSZ (128*PSTR)
#define PSTG (4*PLSZ)
#define PNIT 32

__device__ __forceinline__ void pstage(uint32_t sbase, const uint32_t* __restrict__ XH,
                                       const uint32_t* __restrict__ XL,
                                       const uint32_t* __restrict__ WH,
                                       const uint32_t* __restrict__ WL,
                                       int m0, int n0, int it, int tid)
{
    #pragma unroll
    for (int i = 0; i < 2; i++) {
        int e = tid + i * 256;
        int r = e >> 2, c = e & 3;
        uint32_t o = (uint32_t)(r * PSTR + c * 4) * 4;
        const size_t gi = (size_t)(m0 + r) * 512 + it * 16 + c * 4;
        cp16s(sbase + o,              XH + gi);
        cp16s(sbase + PLSZ*4 + o,     XL + gi);
        const size_t gw = (size_t)(n0 + r) * 512 + it * 16 + c * 4;
        cp16s(sbase + 2*PLSZ*4 + o,   WH + gw);
        cp16s(sbase + 3*PLSZ*4 + o,   WL + gw);
    }
}

__global__ __launch_bounds__(256, 2) void proj_tc(
    const float* __restrict__ Bq, const float* __restrict__ Bk, const float* __restrict__ Bv)
{
    extern __shared__ uint32_t sm[];
    const uint32_t sb = smem_u32(sm);

    const int tid = threadIdx.x;
    const int z = blockIdx.z;
    const uint32_t* XH = g_XH + (size_t)z * 4096 * 512;
    const uint32_t* XL = g_XL + (size_t)z * 4096 * 512;
    const uint32_t* WH = g_WH + (size_t)z * 1024 * 512;
    const uint32_t* WL = g_WL + (size_t)z * 1024 * 512;
    const float* Bi = (z == 0) ? Bq : (z == 1) ? Bk : Bv;
    const float scale = (z == 0) ? 0.125f : 1.0f;

    const int m0 = blockIdx.y * 128;
    const int n0 = blockIdx.x * 128;

    const int warp = tid >> 5, lane = tid & 31;
    const int g = lane >> 2, tig = lane & 3;
    const int wm = warp >> 1, wn = warp & 1;
    const int mid = lane >> 3, lr = lane & 7;
    const int arowl = (mid & 1) * 8 + lr, acol = (mid >> 1) * 4;
    const int browl = (mid >> 1) * 8 + lr, bcol = (mid & 1) * 4;

    float cfr[2][8][4];
    #pragma unroll
    for (int mt = 0; mt < 2; mt++)
        #pragma unroll
        for (int nt = 0; nt < 8; nt++)
            #pragma unroll
            for (int e = 0; e < 4; e++) cfr[mt][nt][e] = 0.f;

    pstage(sb, XH, XL, WH, WL, m0, n0, 0, tid);
    CP_COMMIT();

    for (int it = 0; it < PNIT; it++) {
        if (it + 1 < PNIT)
            pstage(sb + ((it + 1) & 1) * PSTG * 4, XH, XL, WH, WL, m0, n0, it + 1, tid);
        CP_COMMIT();
        CP_WAIT1();
        __syncthreads();

        const uint32_t AHb = sb + ((it & 1) * PSTG) * 4;
        const uint32_t ALb = AHb + PLSZ * 4;
        const uint32_t BHb = AHb + 2 * PLSZ * 4;
        const uint32_t BLb = AHb + 3 * PLSZ * 4;

        #pragma unroll
        for (int kg = 0; kg < 2; kg++) {
            const int kgb = kg * 8;
            uint32_t ah[2][4], al[2][4];
            #pragma unroll
            for (int mt = 0; mt < 2; mt++) {
                const uint32_t oa = (uint32_t)((wm*32 + mt*16 + arowl) * PSTR + kgb + acol) * 4;
                ldsm4(ah[mt], AHb + oa);
                ldsm4(al[mt], ALb + oa);
            }
            #pragma unroll
            for (int np = 0; np < 4; np++) {
                const int nt0 = 2 * np;
                const uint32_t ob = (uint32_t)((wn*64 + nt0*8 + browl) * PSTR + kgb + bcol) * 4;
                uint32_t bh[4], bl[4];
                ldsm4(bh, BHb + ob);
                ldsm4(bl, BLb + ob);
                #pragma unroll
                for (int mt = 0; mt < 2; mt++) {
                    mma16(cfr[mt][nt0],   ah[mt], bl);
                    mma16(cfr[mt][nt0],   al[mt], bh);
                    mma16(cfr[mt][nt0],   ah[mt], bh);
                    mma16(cfr[mt][nt0+1], ah[mt], bl + 2);
                    mma16(cfr[mt][nt0+1], al[mt], bh + 2);
                    mma16(cfr[mt][nt0+1], ah[mt], bh + 2);
                }
            }
        }
        __syncthreads();
    }

    float* Cs = (float*)sm;
    #pragma unroll
    for (int mt = 0; mt < 2; mt++) {
        const int rm = wm * 32 + mt * 16 + g;
        #pragma unroll
        for (int nt = 0; nt < 8; nt++) {
            const int cn = wn * 64 + nt * 8 + 2 * tig;
            Cs[(rm    ) * 132 + cn    ] = cfr[mt][nt][0];
            Cs[(rm    ) * 132 + cn + 1] = cfr[mt][nt][1];
            Cs[(rm + 8) * 132 + cn    ] = cfr[mt][nt][2];
            Cs[(rm + 8) * 132 + cn + 1] = cfr[mt][nt][3];
        }
    }
    __syncthreads();

    if (z < 2) {
        uint32_t* OH = (z == 0) ? g_QH : g_KH;
        uint32_t* OL = (z == 0) ? g_QL : g_KL;
        const int qcol = (tid & 15) * 4;
        #pragma unroll
        for (int hh = 0; hh < 2; hh++) {
            const int h = ((n0 + hh * 64) >> 6);
            const float4 bv = *(const float4*)(Bi + n0 + hh * 64 + qcol);
            #pragma unroll
            for (int p = 0; p < 8; p++) {
                const int idx = tid + p * 256;
                const int m = idx >> 4;
                const int gm = m0 + m, b = gm >> 10, s = gm & (NS - 1);
                const float* src = Cs + m * 132 + hh * 64 + qcol;
                float v0 = (src[0] + bv.x) * scale;
                float v1 = (src[1] + bv.y) * scale;
                float v2 = (src[2] + bv.z) * scale;
                float v3 = (src[3] + bv.w) * scale;
                uint32_t h0, l0, h1, l1;
                split2(v0, v1, h0, l0);
                split2(v2, v3, h1, l1);
                const size_t o = ((size_t)(b * NH + h) * NS + s) * 32 + (qcol >> 1);
                *(uint2*)(OH + o) = make_uint2(h0, h1);
                *(uint2*)(OL + o) = make_uint2(l0, l1);
            }
        }
    } else {
        #pragma unroll 1
        for (int p = 0; p < 32; p++) {
            const int e = tid + p * 256;
            const int sp = e & 63;
            const int dl = e >> 6;
            const int n = n0 + dl;
            const int h = n >> 6, dd = n & 63;
            const int gm = m0 + 2 * sp;
            const int b = gm >> 10;
            const int spg = (gm & (NS - 1)) >> 1;
            const float bi = Bi[n];
            float v0 = Cs[(2*sp    ) * 132 + dl] + bi;
            float v1 = Cs[(2*sp + 1) * 132 + dl] + bi;
            uint32_t hh, ll;
            split2(v0, v1, hh, ll);
            const size_t o = ((size_t)(b * NH + h) * 64 + dd) * 512 + spg;
            g_VH[o] = hh;
            g_VL[o] = ll;
        }
    }
}

// ---------------------------------------------------------------------------
// bf16x3 flash attention, v6: R11 3-stage/1-barrier structure + bitmask.
// Mask words (4 LDG.32/warp-tile) issued before score MMAs -> latency hidden.
// ---------------------------------------------------------------------------
#define ASTR 36
#define APL (64*ASTR)
#define ASTG (4*APL)
#define NSTAGE 3

__device__ __forceinline__ void aload(uint32_t sb, int stage, int j0,
                                      const uint32_t* __restrict__ KHg,
                                      const uint32_t* __restrict__ KLg,
                                      const uint32_t* __restrict__ VHg,
                                      const uint32_t* __restrict__ VLg, int tid)
{
    const uint32_t base = sb + (uint32_t)stage * ASTG * 4;
    #pragma unroll
    for (int i = 0; i < 2; i++) {
        int e = tid + i * 256;
        int r = e >> 3, c = e & 7;
        uint32_t o = (uint32_t)(r * ASTR + c * 4) * 4;
        const size_t gk = (size_t)(j0 + r) * 32 + c * 4;
        cp16s(base + o,            KHg + gk);
        cp16s(base + APL*4 + o,    KLg + gk);
        const size_t gv = (size_t)r * 512 + (j0 >> 1) + c * 4;
        cp16s(base + 2*APL*4 + o,  VHg + gv);
        cp16s(base + 3*APL*4 + o,  VLg + gv);
    }
}

__global__ __launch_bounds__(256, 2) void attn_tc(float* __restrict__ out)
{
    extern __shared__ uint32_t s[];
    const uint32_t sb = smem_u32(s);

    const int b = blockIdx.z, h = blockIdx.y;
    const int q0 = blockIdx.x * 128;
    const int tid = threadIdx.x, warp = tid >> 5, lane = tid & 31;
    const int g = lane >> 2, tig = lane & 3;
    const int r0 = warp * 16 + g;
    const int mid = lane >> 3, lr = lane & 7;
    const int browl = (mid >> 1) * 8 + lr, bcol = (mid & 1) * 4;

    const size_t bh32 = (size_t)(b * NH + h) * NS * 32;
    const uint32_t* QHg = g_QH + bh32;
    const uint32_t* QLg = g_QL + bh32;
    const uint32_t* KHg = g_KH + bh32;
    const uint32_t* KLg = g_KL + bh32;
    const size_t bhv = (size_t)(b * NH + h) * 64 * 512;
    const uint32_t* VHg = g_VH + bhv;
    const uint32_t* VLg = g_VL + bhv;
    const uint32_t* Mr0 = g_MB + ((size_t)b * NS + q0 + r0) * 32;   // row r0
    const uint32_t* Mr1 = Mr0 + 8 * 32;                             // row r0+8

    // --- Q bounce through stage0/1 KH/KL planes, then frags -> registers ---
    #pragma unroll
    for (int i = 0; i < 4; i++) {
        int e = tid + i * 256;
        int vr = e >> 3, c = e & 7;
        uint32_t idx = (uint32_t)(vr >> 6) * ASTG + (uint32_t)(vr & 63) * ASTR + c * 4;
        *(uint4*)(s + idx)       = *(const uint4*)(QHg + (size_t)(q0 + vr) * 32 + c * 4);
        *(uint4*)(s + idx + APL) = *(const uint4*)(QLg + (size_t)(q0 + vr) * 32 + c * 4);
    }
    __syncthreads();
    uint32_t qh[4][4], ql[4][4];
    {
        const uint32_t qbase = (uint32_t)(r0 >> 6) * ASTG;
        const int lrq = r0 & 63;
        #pragma unroll
        for (int kg = 0; kg < 4; kg++) {
            const int kp1 = kg * 8 + tig, kp2 = kp1 + 4;
            qh[kg][0] = s[qbase + lrq*ASTR + kp1]; qh[kg][1] = s[qbase + (lrq+8)*ASTR + kp1];
            qh[kg][2] = s[qbase + lrq*ASTR + kp2]; qh[kg][3] = s[qbase + (lrq+8)*ASTR + kp2];
            ql[kg][0] = s[qbase + APL + lrq*ASTR + kp1]; ql[kg][1] = s[qbase + APL + (lrq+8)*ASTR + kp1];
            ql[kg][2] = s[qbase + APL + lrq*ASTR + kp2]; ql[kg][3] = s[qbase + APL + (lrq+8)*ASTR + kp2];
        }
    }
    __syncthreads();

    float o[8][4];
    #pragma unroll
    for (int nt = 0; nt < 8; nt++)
        #pragma unroll
        for (int e = 0; e < 4; e++) o[nt][e] = 0.f;
    float mrow[2] = {-3.4e38f, -3.4e38f};
    float lsum[2] = {0.f, 0.f};

    aload(sb, 0, 0, KHg, KLg, VHg, VLg, tid);
    CP_COMMIT();
    aload(sb, 1, 64, KHg, KLg, VHg, VLg, tid);
    CP_COMMIT();

    for (int jt = 0; jt < NS/64; jt++) {
        CP_WAIT1();            // own copies of stage jt%3 have landed
        __syncthreads();       // publishes stage jt; proves stage (jt+2)%3 free
        if (jt + 2 < NS/64)
            aload(sb, (jt + 2) % NSTAGE, (jt + 2) * 64, KHg, KLg, VHg, VLg, tid);
        CP_COMMIT();           // unconditional: uniform group counts

        // mask words for this tile — issued early, consumed after score MMAs
        const uint32_t mwa0 = Mr0[jt*2], mwa1 = Mr0[jt*2 + 1];
        const uint32_t mwb0 = Mr1[jt*2], mwb1 = Mr1[jt*2 + 1];

        const uint32_t KHb = sb + ((jt % NSTAGE) * ASTG) * 4;
        const uint32_t KLb = KHb + APL * 4;
        const uint32_t VHb = KHb + 2 * APL * 4;
        const uint32_t VLb = KHb + 3 * APL * 4;

        // ---- scores S[16x64] per warp, bf16x3, ldmatrix B-frags ----
        float c[8][4];
        #pragma unroll
        for (int nt = 0; nt < 8; nt++)
            #pragma unroll
            for (int e = 0; e < 4; e++) c[nt][e] = 0.f;

        #pragma unroll
        for (int kg = 0; kg < 4; kg++) {
            const int kgb = kg * 8;
            #pragma unroll
            for (int np = 0; np < 4; np++) {
                const int nt0 = 2 * np;
                const uint32_t ob = (uint32_t)((nt0*8 + browl) * ASTR + kgb + bcol) * 4;
                uint32_t kh[4], kl[4];
                ldsm4(kh, KHb + ob);
                ldsm4(kl, KLb + ob);
                mma16(c[nt0],   qh[kg], kl);
                mma16(c[nt0],   ql[kg], kh);
                mma16(c[nt0],   qh[kg], kh);
                mma16(c[nt0+1], qh[kg], kl + 2);
                mma16(c[nt0+1], ql[kg], kh + 2);
                mma16(c[nt0+1], qh[kg], kh + 2);
            }
        }

        // ---- mask from bits: key = nt*8 + 2*tig (+1); word = key>>5 ----
        #pragma unroll
        for (int nt = 0; nt < 8; nt++) {
            const int key = nt * 8 + 2 * tig;
            const uint32_t wa = (nt < 4) ? mwa0 : mwa1;
            const uint32_t wb = (nt < 4) ? mwb0 : mwb1;
            const int bit = key & 31;
            c[nt][0] += ((wa >> bit)       & 1) ? 0.f : -1e6f;
            c[nt][1] += ((wa >> (bit + 1)) & 1) ? 0.f : -1e6f;
            c[nt][2] += ((wb >> bit)       & 1) ? 0.f : -1e6f;
            c[nt][3] += ((wb >> (bit + 1)) & 1) ? 0.f : -1e6f;
        }

        // ---- online softmax ----
        #pragma unroll
        for (int sl = 0; sl < 2; sl++) {
            float cm = -3.4e38f;
            #pragma unroll
            for (int nt = 0; nt < 8; nt++)
                cm = fmaxf(cm, fmaxf(c[nt][2*sl], c[nt][2*sl + 1]));
            cm = fmaxf(cm, __shfl_xor_sync(0xffffffffu, cm, 1));
            cm = fmaxf(cm, __shfl_xor_sync(0xffffffffu, cm, 2));
            const float mn = fmaxf(mrow[sl], cm);
            const float alc = __expf(mrow[sl] - mn);
            mrow[sl] = mn;
            float rs = 0.f;
            #pragma unroll
            for (int nt = 0; nt < 8; nt++) {
                c[nt][2*sl]     = __expf(c[nt][2*sl]     - mn);
                c[nt][2*sl + 1] = __expf(c[nt][2*sl + 1] - mn);
                rs += c[nt][2*sl] + c[nt][2*sl + 1];
            }
            rs += __shfl_xor_sync(0xffffffffu, rs, 1);
            rs += __shfl_xor_sync(0xffffffffu, rs, 2);
            lsum[sl] = lsum[sl] * alc + rs;
            #pragma unroll
            for (int nt = 0; nt < 8; nt++) {
                o[nt][2*sl]     *= alc;
                o[nt][2*sl + 1] *= alc;
            }
        }

        // ---- O += P @ V, ldmatrix V-frags ----
        #pragma unroll
        for (int q = 0; q < 4; q++) {
            uint32_t ph[4], pl[4];
            split2(c[2*q    ][0], c[2*q    ][1], ph[0], pl[0]);
            split2(c[2*q    ][2], c[2*q    ][3], ph[1], pl[1]);
            split2(c[2*q + 1][0], c[2*q + 1][1], ph[2], pl[2]);
            split2(c[2*q + 1][2], c[2*q + 1][3], ph[3], pl[3]);
            const int jb = q * 8;
            #pragma unroll
            for (int np = 0; np < 4; np++) {
                const int nt0 = 2 * np;
                const uint32_t ob = (uint32_t)((nt0*8 + browl) * ASTR + jb + bcol) * 4;
                uint32_t vh[4], vl[4];
                ldsm4(vh, VHb + ob);
                ldsm4(vl, VLb + ob);
                mma16(o[nt0],   ph, vl);
                mma16(o[nt0],   pl, vh);
                mma16(o[nt0],   ph, vh);
                mma16(o[nt0+1], ph, vl + 2);
                mma16(o[nt0+1], pl, vh + 2);
                mma16(o[nt0+1], ph, vh + 2);
            }
        }
        // no trailing barrier: next iteration's leading barrier + 3-stage ring
    }

    // ---- epilogue ----
    const float inv0 = 1.0f / lsum[0];
    const float inv1 = 1.0f / lsum[1];
    float* orow = out + ((size_t)b*NS + (q0 + r0))*NE + h*ND + 2*tig;
    #pragma unroll
    for (int nt = 0; nt < 8; nt++) {
        *(float2*)(orow + nt*8) = make_float2(o[nt][0]*inv0, o[nt][1]*inv0);
        *(float2*)(orow + (size_t)8*NE + nt*8) = make_float2(o[nt][2]*inv1, o[nt][3]*inv1);
    }
}

extern "C" void kernel_launch(void* const* d_in, const int* in_sizes, int n_in,
                              void* d_out, int out_size)
{
    const float* query = (const float*)d_in[0];
    const float* key   = (const float*)d_in[1];
    const float* value = (const float*)d_in[2];
    const float* mask  = (const float*)d_in[3];
    const float* Wq    = (const float*)d_in[4];
    const float* bq    = (const float*)d_in[5];
    const float* Wk    = (const float*)d_in[6];
    const float* bk    = (const float*)d_in[7];
    const float* Wv    = (const float*)d_in[8];
    const float* bv    = (const float*)d_in[9];
    float* out = (float*)d_out;

    split_in<<<dim3(512, 7), 256>>>(query, key, value, Wq, Wk, Wv, mask);

    const int proj_smem = 2 * PSTG * 4;   // 81920 B
    cudaFuncSetAttribute(proj_tc, cudaFuncAttributeMaxDynamicSharedMemorySize, proj_smem);
    dim3 pg(NE / 128, (NB * NS) / 128, 3);
    proj_tc<<<pg, 256, proj_smem>>>(bq, bk, bv);

    const int attn_smem = NSTAGE * ASTG * 4;   // 110592 B
    cudaFuncSetAttribute(attn_tc, cudaFuncAttributeMaxDynamicSharedMemorySize, attn_smem);
    dim3 ag(NS/128, NH, NB);
    attn_tc<<<ag, 256, attn_smem>>>(out);
}

// round 14
// speedup vs baseline: 1.0814x; 1.0048x over previous
#include <cuda_runtime.h>
#include <cstdint>
#include <math.h>

#define NB 4
#define NH 16
#define NS 1024
#define ND 64
#define NE 1024

// ---------------------------------------------------------------------------
// Global scratch: bf16 hi/lo packed planes (u32 = 2 bf16, consecutive k).
// ---------------------------------------------------------------------------
__device__ uint32_t g_XH[3 * 4096 * 512];   // inputs  [z][m][kp]
__device__ uint32_t g_XL[3 * 4096 * 512];
__device__ uint32_t g_WH[3 * 1024 * 512];   // weights [z][n][kp]
__device__ uint32_t g_WL[3 * 1024 * 512];
__device__ uint32_t g_QH[NB*NH*NS*32];      // Q/K: [(b,h)][s][dp]
__device__ uint32_t g_QL[NB*NH*NS*32];
__device__ uint32_t g_KH[NB*NH*NS*32];
__device__ uint32_t g_KL[NB*NH*NS*32];
__device__ uint32_t g_VH[NB*NH*64*512];     // V: [(b,h)][d][sp]  (key-pair packed)
__device__ uint32_t g_VL[NB*NH*64*512];
__device__ uint32_t g_MB[NB*NS*32];         // mask bits: [b][q_row][key_word]

// ---------------------------------------------------------------------------
// helpers
// ---------------------------------------------------------------------------
__device__ __forceinline__ uint32_t smem_u32(const void* p) {
    uint32_t a;
    asm("{ .reg .u64 t; cvta.to.shared.u64 t, %1; cvt.u32.u64 %0, t; }" : "=r"(a) : "l"(p));
    return a;
}
__device__ __forceinline__ void cp16s(uint32_t dst, const void* src) {
    asm volatile("cp.async.cg.shared.global [%0], [%1], 16;" :: "r"(dst), "l"(src));
}
#define CP_COMMIT() asm volatile("cp.async.commit_group;" ::: "memory")
#define CP_WAIT0()  asm volatile("cp.async.wait_group 0;"  ::: "memory")
#define CP_WAIT1()  asm volatile("cp.async.wait_group 1;"  ::: "memory")

__device__ __forceinline__ uint32_t packbf(float e0, float e1) {
    uint32_t r; asm("cvt.rn.bf16x2.f32 %0, %1, %2;" : "=r"(r) : "f"(e1), "f"(e0)); return r;
}
__device__ __forceinline__ void split2(float x0, float x1, uint32_t& h, uint32_t& l) {
    h = packbf(x0, x1);
    float h0 = __uint_as_float(h << 16);
    float h1 = __uint_as_float(h & 0xffff0000u);
    l = packbf(x0 - h0, x1 - h1);
}

// bf16 m16n8k16 mma.sync
__device__ __forceinline__ void mma16(float* d, const uint32_t* a, const uint32_t* b) {
    asm volatile(
        "mma.sync.aligned.m16n8k16.row.col.f32.bf16.bf16.f32 "
        "{%0,%1,%2,%3}, {%4,%5,%6,%7}, {%8,%9}, {%0,%1,%2,%3};"
        : "+f"(d[0]), "+f"(d[1]), "+f"(d[2]), "+f"(d[3])
        : "r"(a[0]), "r"(a[1]), "r"(a[2]), "r"(a[3]), "r"(b[0]), "r"(b[1]));
}

// ldmatrix x4
__device__ __forceinline__ void ldsm4(uint32_t* r, uint32_t addr) {
    asm volatile("ldmatrix.sync.aligned.m8n8.x4.shared.b16 {%0,%1,%2,%3}, [%4];"
        : "=r"(r[0]), "=r"(r[1]), "=r"(r[2]), "=r"(r[3]) : "r"(addr));
}

// ---------------------------------------------------------------------------
// Pre-pass: split 6 fp32 tensors into bf16 hi/lo planes; bitpack the mask.
// ---------------------------------------------------------------------------
__global__ void split_in(const float* __restrict__ q, const float* __restrict__ k,
                         const float* __restrict__ v, const float* __restrict__ wq,
                         const float* __restrict__ wk, const float* __restrict__ wv,
                         const float* __restrict__ mk)
{
    const int z = blockIdx.y;
    if (z == 6) {
        const int nwords = NB * NS * 32;
        for (int i = blockIdx.x * blockDim.x + threadIdx.x; i < nwords;
             i += gridDim.x * blockDim.x) {
            const float4* msrc = (const float4*)(mk + (size_t)i * 32);
            uint32_t w = 0;
            #pragma unroll
            for (int qd = 0; qd < 8; qd++) {
                float4 m4 = msrc[qd];
                w |= (m4.x > 0.5f ? 1u : 0u) << (4*qd);
                w |= (m4.y > 0.5f ? 2u : 0u) << (4*qd);
                w |= (m4.z > 0.5f ? 4u : 0u) << (4*qd);
                w |= (m4.w > 0.5f ? 8u : 0u) << (4*qd);
            }
            g_MB[i] = w;
        }
        return;
    }
    const float* src; uint32_t* H; uint32_t* L; int n;
    if (z < 3) {
        src = (z == 0) ? q : (z == 1) ? k : v;
        H = g_XH + (size_t)z * 4096 * 512; L = g_XL + (size_t)z * 4096 * 512;
        n = 4096 * 512;
    } else {
        src = (z == 3) ? wq : (z == 4) ? wk : wv;
        H = g_WH + (size_t)(z - 3) * 1024 * 512; L = g_WL + (size_t)(z - 3) * 1024 * 512;
        n = 1024 * 512;
    }
    for (int i = blockIdx.x * blockDim.x + threadIdx.x; i < n; i += gridDim.x * blockDim.x) {
        float2 x = ((const float2*)src)[i];
        uint32_t h, l; split2(x.x, x.y, h, l);
        H[i] = h; L[i] = l;
    }
}

// ---------------------------------------------------------------------------
// bf16x3 projection, v3: ONE barrier per K-iteration (R11/R12-proven reorder,
// this time WITHOUT the harmful mask prefetch). wait0 -> barrier (publishes
// stage it, proves stage (it+1)%2 free) -> prefetch -> compute.
// ---------------------------------------------------------------------------
#define PSTR 20
#define PLSZ (128*PSTR)
#define PSTG (4*PLSZ)
#define PNIT 32

__device__ __forceinline__ void pstage(uint32_t sbase, const uint32_t* __restrict__ XH,
                                       const uint32_t* __restrict__ XL,
                                       const uint32_t* __restrict__ WH,
                                       const uint32_t* __restrict__ WL,
                                       int m0, int n0, int it, int tid)
{
    #pragma unroll
    for (int i = 0; i < 2; i++) {
        int e = tid + i * 256;
        int r = e >> 2, c = e & 3;
        uint32_t o = (uint32_t)(r * PSTR + c * 4) * 4;
        const size_t gi = (size_t)(m0 + r) * 512 + it * 16 + c * 4;
        cp16s(sbase + o,              XH + gi);
        cp16s(sbase + PLSZ*4 + o,     XL + gi);
        const size_t gw = (size_t)(n0 + r) * 512 + it * 16 + c * 4;
        cp16s(sbase + 2*PLSZ*4 + o,   WH + gw);
        cp16s(sbase + 3*PLSZ*4 + o,   WL + gw);
    }
}

__global__ __launch_bounds__(256, 2) void proj_tc(
    const float* __restrict__ Bq, const float* __restrict__ Bk, const float* __restrict__ Bv)
{
    extern __shared__ uint32_t sm[];
    const uint32_t sb = smem_u32(sm);

    const int tid = threadIdx.x;
    const int z = blockIdx.z;
    const uint32_t* XH = g_XH + (size_t)z * 4096 * 512;
    const uint32_t* XL = g_XL + (size_t)z * 4096 * 512;
    const uint32_t* WH = g_WH + (size_t)z * 1024 * 512;
    const uint32_t* WL = g_WL + (size_t)z * 1024 * 512;
    const float* Bi = (z == 0) ? Bq : (z == 1) ? Bk : Bv;
    const float scale = (z == 0) ? 0.125f : 1.0f;

    const int m0 = blockIdx.y * 128;
    const int n0 = blockIdx.x * 128;

    const int warp = tid >> 5, lane = tid & 31;
    const int g = lane >> 2, tig = lane & 3;
    const int wm = warp >> 1, wn = warp & 1;
    const int mid = lane >> 3, lr = lane & 7;
    const int arowl = (mid & 1) * 8 + lr, acol = (mid >> 1) * 4;
    const int browl = (mid >> 1) * 8 + lr, bcol = (mid & 1) * 4;

    float cfr[2][8][4];
    #pragma unroll
    for (int mt = 0; mt < 2; mt++)
        #pragma unroll
        for (int nt = 0; nt < 8; nt++)
            #pragma unroll
            for (int e = 0; e < 4; e++) cfr[mt][nt][e] = 0.f;

    pstage(sb, XH, XL, WH, WL, m0, n0, 0, tid);
    CP_COMMIT();

    for (int it = 0; it < PNIT; it++) {
        CP_WAIT0();            // stage it%2 landed (own copies)
        __syncthreads();       // publish stage it; stage (it+1)%2 provably free
        if (it + 1 < PNIT)
            pstage(sb + ((it + 1) & 1) * PSTG * 4, XH, XL, WH, WL, m0, n0, it + 1, tid);
        CP_COMMIT();

        const uint32_t AHb = sb + ((it & 1) * PSTG) * 4;
        const uint32_t ALb = AHb + PLSZ * 4;
        const uint32_t BHb = AHb + 2 * PLSZ * 4;
        const uint32_t BLb = AHb + 3 * PLSZ * 4;

        #pragma unroll
        for (int kg = 0; kg < 2; kg++) {
            const int kgb = kg * 8;
            uint32_t ah[2][4], al[2][4];
            #pragma unroll
            for (int mt = 0; mt < 2; mt++) {
                const uint32_t oa = (uint32_t)((wm*32 + mt*16 + arowl) * PSTR + kgb + acol) * 4;
                ldsm4(ah[mt], AHb + oa);
                ldsm4(al[mt], ALb + oa);
            }
            #pragma unroll
            for (int np = 0; np < 4; np++) {
                const int nt0 = 2 * np;
                const uint32_t ob = (uint32_t)((wn*64 + nt0*8 + browl) * PSTR + kgb + bcol) * 4;
                uint32_t bh[4], bl[4];
                ldsm4(bh, BHb + ob);
                ldsm4(bl, BLb + ob);
                #pragma unroll
                for (int mt = 0; mt < 2; mt++) {
                    mma16(cfr[mt][nt0],   ah[mt], bl);
                    mma16(cfr[mt][nt0],   al[mt], bh);
                    mma16(cfr[mt][nt0],   ah[mt], bh);
                    mma16(cfr[mt][nt0+1], ah[mt], bl + 2);
                    mma16(cfr[mt][nt0+1], al[mt], bh + 2);
                    mma16(cfr[mt][nt0+1], ah[mt], bh + 2);
                }
            }
        }
        // no trailing barrier: next iteration's leading barrier covers reuse
    }
    __syncthreads();           // all compute done before Cs overwrites stages

    float* Cs = (float*)sm;
    #pragma unroll
    for (int mt = 0; mt < 2; mt++) {
        const int rm = wm * 32 + mt * 16 + g;
        #pragma unroll
        for (int nt = 0; nt < 8; nt++) {
            const int cn = wn * 64 + nt * 8 + 2 * tig;
            Cs[(rm    ) * 132 + cn    ] = cfr[mt][nt][0];
            Cs[(rm    ) * 132 + cn + 1] = cfr[mt][nt][1];
            Cs[(rm + 8) * 132 + cn    ] = cfr[mt][nt][2];
            Cs[(rm + 8) * 132 + cn + 1] = cfr[mt][nt][3];
        }
    }
    __syncthreads();

    if (z < 2) {
        uint32_t* OH = (z == 0) ? g_QH : g_KH;
        uint32_t* OL = (z == 0) ? g_QL : g_KL;
        const int qcol = (tid & 15) * 4;
        #pragma unroll
        for (int hh = 0; hh < 2; hh++) {
            const int h = ((n0 + hh * 64) >> 6);
            const float4 bv = *(const float4*)(Bi + n0 + hh * 64 + qcol);
            #pragma unroll
            for (int p = 0; p < 8; p++) {
                const int idx = tid + p * 256;
                const int m = idx >> 4;
                const int gm = m0 + m, b = gm >> 10, s = gm & (NS - 1);
                const float* src = Cs + m * 132 + hh * 64 + qcol;
                float v0 = (src[0] + bv.x) * scale;
                float v1 = (src[1] + bv.y) * scale;
                float v2 = (src[2] + bv.z) * scale;
                float v3 = (src[3] + bv.w) * scale;
                uint32_t h0, l0, h1, l1;
                split2(v0, v1, h0, l0);
                split2(v2, v3, h1, l1);
                const size_t o = ((size_t)(b * NH + h) * NS + s) * 32 + (qcol >> 1);
                *(uint2*)(OH + o) = make_uint2(h0, h1);
                *(uint2*)(OL + o) = make_uint2(l0, l1);
            }
        }
    } else {
        #pragma unroll 1
        for (int p = 0; p < 32; p++) {
            const int e = tid + p * 256;
            const int sp = e & 63;
            const int dl = e >> 6;
            const int n = n0 + dl;
            const int h = n >> 6, dd = n & 63;
            const int gm = m0 + 2 * sp;
            const int b = gm >> 10;
            const int spg = (gm & (NS - 1)) >> 1;
            const float bi = Bi[n];
            float v0 = Cs[(2*sp    ) * 132 + dl] + bi;
            float v1 = Cs[(2*sp + 1) * 132 + dl] + bi;
            uint32_t hh, ll;
            split2(v0, v1, hh, ll);
            const size_t o = ((size_t)(b * NH + h) * 64 + dd) * 512 + spg;
            g_VH[o] = hh;
            g_VL[o] = ll;
        }
    }
}

// ---------------------------------------------------------------------------
// bf16x3 flash attention, v6 (unchanged from R13: 3-stage/1-barrier + bitmask).
// ---------------------------------------------------------------------------
#define ASTR 36
#define APL (64*ASTR)
#define ASTG (4*APL)
#define NSTAGE 3

__device__ __forceinline__ void aload(uint32_t sb, int stage, int j0,
                                      const uint32_t* __restrict__ KHg,
                                      const uint32_t* __restrict__ KLg,
                                      const uint32_t* __restrict__ VHg,
                                      const uint32_t* __restrict__ VLg, int tid)
{
    const uint32_t base = sb + (uint32_t)stage * ASTG * 4;
    #pragma unroll
    for (int i = 0; i < 2; i++) {
        int e = tid + i * 256;
        int r = e >> 3, c = e & 7;
        uint32_t o = (uint32_t)(r * ASTR + c * 4) * 4;
        const size_t gk = (size_t)(j0 + r) * 32 + c * 4;
        cp16s(base + o,            KHg + gk);
        cp16s(base + APL*4 + o,    KLg + gk);
        const size_t gv = (size_t)r * 512 + (j0 >> 1) + c * 4;
        cp16s(base + 2*APL*4 + o,  VHg + gv);
        cp16s(base + 3*APL*4 + o,  VLg + gv);
    }
}

__global__ __launch_bounds__(256, 2) void attn_tc(float* __restrict__ out)
{
    extern __shared__ uint32_t s[];
    const uint32_t sb = smem_u32(s);

    const int b = blockIdx.z, h = blockIdx.y;
    const int q0 = blockIdx.x * 128;
    const int tid = threadIdx.x, warp = tid >> 5, lane = tid & 31;
    const int g = lane >> 2, tig = lane & 3;
    const int r0 = warp * 16 + g;
    const int mid = lane >> 3, lr = lane & 7;
    const int browl = (mid >> 1) * 8 + lr, bcol = (mid & 1) * 4;

    const size_t bh32 = (size_t)(b * NH + h) * NS * 32;
    const uint32_t* QHg = g_QH + bh32;
    const uint32_t* QLg = g_QL + bh32;
    const uint32_t* KHg = g_KH + bh32;
    const uint32_t* KLg = g_KL + bh32;
    const size_t bhv = (size_t)(b * NH + h) * 64 * 512;
    const uint32_t* VHg = g_VH + bhv;
    const uint32_t* VLg = g_VL + bhv;
    const uint32_t* Mr0 = g_MB + ((size_t)b * NS + q0 + r0) * 32;
    const uint32_t* Mr1 = Mr0 + 8 * 32;

    // --- Q bounce through stage0/1 KH/KL planes, then frags -> registers ---
    #pragma unroll
    for (int i = 0; i < 4; i++) {
        int e = tid + i * 256;
        int vr = e >> 3, c = e & 7;
        uint32_t idx = (uint32_t)(vr >> 6) * ASTG + (uint32_t)(vr & 63) * ASTR + c * 4;
        *(uint4*)(s + idx)       = *(const uint4*)(QHg + (size_t)(q0 + vr) * 32 + c * 4);
        *(uint4*)(s + idx + APL) = *(const uint4*)(QLg + (size_t)(q0 + vr) * 32 + c * 4);
    }
    __syncthreads();
    uint32_t qh[4][4], ql[4][4];
    {
        const uint32_t qbase = (uint32_t)(r0 >> 6) * ASTG;
        const int lrq = r0 & 63;
        #pragma unroll
        for (int kg = 0; kg < 4; kg++) {
            const int kp1 = kg * 8 + tig, kp2 = kp1 + 4;
            qh[kg][0] = s[qbase + lrq*ASTR + kp1]; qh[kg][1] = s[qbase + (lrq+8)*ASTR + kp1];
            qh[kg][2] = s[qbase + lrq*ASTR + kp2]; qh[kg][3] = s[qbase + (lrq+8)*ASTR + kp2];
            ql[kg][0] = s[qbase + APL + lrq*ASTR + kp1]; ql[kg][1] = s[qbase + APL + (lrq+8)*ASTR + kp1];
            ql[kg][2] = s[qbase + APL + lrq*ASTR + kp2]; ql[kg][3] = s[qbase + APL + (lrq+8)*ASTR + kp2];
        }
    }
    __syncthreads();

    float o[8][4];
    #pragma unroll
    for (int nt = 0; nt < 8; nt++)
        #pragma unroll
        for (int e = 0; e < 4; e++) o[nt][e] = 0.f;
    float mrow[2] = {-3.4e38f, -3.4e38f};
    float lsum[2] = {0.f, 0.f};

    aload(sb, 0, 0, KHg, KLg, VHg, VLg, tid);
    CP_COMMIT();
    aload(sb, 1, 64, KHg, KLg, VHg, VLg, tid);
    CP_COMMIT();

    for (int jt = 0; jt < NS/64; jt++) {
        CP_WAIT1();            // own copies of stage jt%3 have landed
        __syncthreads();       // publishes stage jt; proves stage (jt+2)%3 free
        if (jt + 2 < NS/64)
            aload(sb, (jt + 2) % NSTAGE, (jt + 2) * 64, KHg, KLg, VHg, VLg, tid);
        CP_COMMIT();           // unconditional: uniform group counts

        const uint32_t mwa0 = Mr0[jt*2], mwa1 = Mr0[jt*2 + 1];
        const uint32_t mwb0 = Mr1[jt*2], mwb1 = Mr1[jt*2 + 1];

        const uint32_t KHb = sb + ((jt % NSTAGE) * ASTG) * 4;
        const uint32_t KLb = KHb + APL * 4;
        const uint32_t VHb = KHb + 2 * APL * 4;
        const uint32_t VLb = KHb + 3 * APL * 4;

        // ---- scores S[16x64] per warp, bf16x3, ldmatrix B-frags ----
        float c[8][4];
        #pragma unroll
        for (int nt = 0; nt < 8; nt++)
            #pragma unroll
            for (int e = 0; e < 4; e++) c[nt][e] = 0.f;

        #pragma unroll
        for (int kg = 0; kg < 4; kg++) {
            const int kgb = kg * 8;
            #pragma unroll
            for (int np = 0; np < 4; np++) {
                const int nt0 = 2 * np;
                const uint32_t ob = (uint32_t)((nt0*8 + browl) * ASTR + kgb + bcol) * 4;
                uint32_t kh[4], kl[4];
                ldsm4(kh, KHb + ob);
                ldsm4(kl, KLb + ob);
                mma16(c[nt0],   qh[kg], kl);
                mma16(c[nt0],   ql[kg], kh);
                mma16(c[nt0],   qh[kg], kh);
                mma16(c[nt0+1], qh[kg], kl + 2);
                mma16(c[nt0+1], ql[kg], kh + 2);
                mma16(c[nt0+1], qh[kg], kh + 2);
            }
        }

        // ---- mask from bits ----
        #pragma unroll
        for (int nt = 0; nt < 8; nt++) {
            const int key = nt * 8 + 2 * tig;
            const uint32_t wa = (nt < 4) ? mwa0 : mwa1;
            const uint32_t wb = (nt < 4) ? mwb0 : mwb1;
            const int bit = key & 31;
            c[nt][0] += ((wa >> bit)       & 1) ? 0.f : -1e6f;
            c[nt][1] += ((wa >> (bit + 1)) & 1) ? 0.f : -1e6f;
            c[nt][2] += ((wb >> bit)       & 1) ? 0.f : -1e6f;
            c[nt][3] += ((wb >> (bit + 1)) & 1) ? 0.f : -1e6f;
        }

        // ---- online softmax ----
        #pragma unroll
        for (int sl = 0; sl < 2; sl++) {
            float cm = -3.4e38f;
            #pragma unroll
            for (int nt = 0; nt < 8; nt++)
                cm = fmaxf(cm, fmaxf(c[nt][2*sl], c[nt][2*sl + 1]));
            cm = fmaxf(cm, __shfl_xor_sync(0xffffffffu, cm, 1));
            cm = fmaxf(cm, __shfl_xor_sync(0xffffffffu, cm, 2));
            const float mn = fmaxf(mrow[sl], cm);
            const float alc = __expf(mrow[sl] - mn);
            mrow[sl] = mn;
            float rs = 0.f;
            #pragma unroll
            for (int nt = 0; nt < 8; nt++) {
                c[nt][2*sl]     = __expf(c[nt][2*sl]     - mn);
                c[nt][2*sl + 1] = __expf(c[nt][2*sl + 1] - mn);
                rs += c[nt][2*sl] + c[nt][2*sl + 1];
            }
            rs += __shfl_xor_sync(0xffffffffu, rs, 1);
            rs += __shfl_xor_sync(0xffffffffu, rs, 2);
            lsum[sl] = lsum[sl] * alc + rs;
            #pragma unroll
            for (int nt = 0; nt < 8; nt++) {
                o[nt][2*sl]     *= alc;
                o[nt][2*sl + 1] *= alc;
            }
        }

        // ---- O += P @ V, ldmatrix V-frags ----
        #pragma unroll
        for (int q = 0; q < 4; q++) {
            uint32_t ph[4], pl[4];
            split2(c[2*q    ][0], c[2*q    ][1], ph[0], pl[0]);
            split2(c[2*q    ][2], c[2*q    ][3], ph[1], pl[1]);
            split2(c[2*q + 1][0], c[2*q + 1][1], ph[2], pl[2]);
            split2(c[2*q + 1][2], c[2*q + 1][3], ph[3], pl[3]);
            const int jb = q * 8;
            #pragma unroll
            for (int np = 0; np < 4; np++) {
                const int nt0 = 2 * np;
                const uint32_t ob = (uint32_t)((nt0*8 + browl) * ASTR + jb + bcol) * 4;
                uint32_t vh[4], vl[4];
                ldsm4(vh, VHb + ob);
                ldsm4(vl, VLb + ob);
                mma16(o[nt0],   ph, vl);
                mma16(o[nt0],   pl, vh);
                mma16(o[nt0],   ph, vh);
                mma16(o[nt0+1], ph, vl + 2);
                mma16(o[nt0+1], pl, vh + 2);
                mma16(o[nt0+1], ph, vh + 2);
            }
        }
        // no trailing barrier: next iteration's leading barrier + 3-stage ring
    }

    // ---- epilogue ----
    const float inv0 = 1.0f / lsum[0];
    const float inv1 = 1.0f / lsum[1];
    float* orow = out + ((size_t)b*NS + (q0 + r0))*NE + h*ND + 2*tig;
    #pragma unroll
    for (int nt = 0; nt < 8; nt++) {
        *(float2*)(orow + nt*8) = make_float2(o[nt][0]*inv0, o[nt][1]*inv0);
        *(float2*)(orow + (size_t)8*NE + nt*8) = make_float2(o[nt][2]*inv1, o[nt][3]*inv1);
    }
}

extern "C" void kernel_launch(void* const* d_in, const int* in_sizes, int n_in,
                              void* d_out, int out_size)
{
    const float* query = (const float*)d_in[0];
    const float* key   = (const float*)d_in[1];
    const float* value = (const float*)d_in[2];
    const float* mask  = (const float*)d_in[3];
    const float* Wq    = (const float*)d_in[4];
    const float* bq    = (const float*)d_in[5];
    const float* Wk    = (const float*)d_in[6];
    const float* bk    = (const float*)d_in[7];
    const float* Wv    = (const float*)d_in[8];
    const float* bv    = (const float*)d_in[9];
    float* out = (float*)d_out;

    split_in<<<dim3(512, 7), 256>>>(query, key, value, Wq, Wk, Wv, mask);

    const int proj_smem = 2 * PSTG * 4;   // 81920 B
    cudaFuncSetAttribute(proj_tc, cudaFuncAttributeMaxDynamicSharedMemorySize, proj_smem);
    dim3 pg(NE / 128, (NB * NS) / 128, 3);
    proj_tc<<<pg, 256, proj_smem>>>(bq, bk, bv);

    const int attn_smem = NSTAGE * ASTG * 4;   // 110592 B
    cudaFuncSetAttribute(attn_tc, cudaFuncAttributeMaxDynamicSharedMemorySize, attn_smem);
    dim3 ag(NS/128, NH, NB);
    attn_tc<<<ag, 256, attn_smem>>>(out);
}